// round 7
// baseline (speedup 1.0000x reference)
#include <cuda_runtime.h>
#include <cstdint>

#define TPB 256

__global__ void __launch_bounds__(TPB) encoder_direct4_kernel(
    const float* __restrict__ x,   // [N,10]
    const float* __restrict__ t,   // [N,1]
    const float* __restrict__ y,   // [N,1]
    const float* __restrict__ w,   // [2048]
    const float* __restrict__ b,   // [2048]
    float* __restrict__ out,       // [N,1]
    int n)
{
    const int tid = blockIdx.x * TPB + threadIdx.x;
    const int i0  = tid * 4;                   // first of 4 rows
    if (i0 >= n) return;

    if (i0 + 3 < n) {
        // ---- fast path: 4 rows = 160B = 10 aligned LDG.128, all front-batched ----
        const float4* xv = (const float4*)(x + (size_t)i0 * 10);
        float f[40];
#pragma unroll
        for (int q = 0; q < 10; ++q) {
            float4 v = __ldg(xv + q);
            f[4 * q + 0] = v.x;
            f[4 * q + 1] = v.y;
            f[4 * q + 2] = v.z;
            f[4 * q + 3] = v.w;
        }
        float4 tv = __ldg((const float4*)(t + i0));   // i0 % 4 == 0 -> 16B aligned
        float4 yv = __ldg((const float4*)(y + i0));
        const float tb[4] = {tv.x, tv.y, tv.z, tv.w};
        const float yb[4] = {yv.x, yv.y, yv.z, yv.w};

        float ob[4];
#pragma unroll
        for (int r = 0; r < 4; ++r) {
            int idx = 0;
#pragma unroll
            for (int j = 0; j < 10; ++j)
                idx = (idx << 1) | (f[10 * r + j] != 0.0f ? 1 : 0);
            idx |= (tb[r] != 0.0f ? 1 : 0) << 10;
            ob[r] = fmaf(yb[r], __ldg(w + idx), __ldg(b + idx));
        }

        float4 o = make_float4(ob[0], ob[1], ob[2], ob[3]);
        *(float4*)(out + i0) = o;
    } else {
        // ---- tail: up to 3 rows, scalar path ----
        for (int i = i0; i < n; ++i) {
            const float* xr = x + (size_t)i * 10;
            int idx = 0;
#pragma unroll
            for (int j = 0; j < 10; ++j)
                idx = (idx << 1) | (xr[j] != 0.0f ? 1 : 0);
            idx |= (t[i] != 0.0f ? 1 : 0) << 10;
            out[i] = fmaf(y[i], __ldg(w + idx), __ldg(b + idx));
        }
    }
}

extern "C" void kernel_launch(void* const* d_in, const int* in_sizes, int n_in,
                              void* d_out, int out_size)
{
    const float* x = (const float*)d_in[0];
    const float* t = (const float*)d_in[1];
    const float* y = (const float*)d_in[2];
    const float* w = (const float*)d_in[3];
    const float* b = (const float*)d_in[4];
    float* out = (float*)d_out;

    int n = in_sizes[1];
    int nthreads = (n + 3) / 4;
    int blocks = (nthreads + TPB - 1) / TPB;
    encoder_direct4_kernel<<<blocks, TPB>>>(x, t, y, w, b, out, n);
}

// round 8
// speedup vs baseline: 1.1471x; 1.1471x over previous
#include <cuda_runtime.h>
#include <cstdint>

#define TPB 256

__global__ void __launch_bounds__(TPB) encoder_direct_pf_kernel(
    const float* __restrict__ x,   // [N,10]
    const float* __restrict__ t,   // [N,1]
    const float* __restrict__ y,   // [N,1]
    const float* __restrict__ w,   // [2048]
    const float* __restrict__ b,   // [2048]
    float* __restrict__ out,       // [N,1]
    int n)
{
    const int tid = blockIdx.x * TPB + threadIdx.x;
    const int i0  = tid * 2;                   // first of 2 rows
    if (i0 >= n) return;

    // ---- L2 prefetch for the thread exactly one grid-wave ahead ----
    // (fire-and-forget: no reg writeback; covers its 80B row-pair)
    {
        const int nthreads = gridDim.x * TPB;          // total threads this launch
        const long long pi = (long long)(tid + nthreads) * 2 * 10;  // float idx
        if (pi < (long long)n * 10) {
            const char* p = (const char*)(x + pi);
            asm volatile("prefetch.global.L2 [%0];" :: "l"(p));
            asm volatile("prefetch.global.L2 [%0];" :: "l"(p + 64));
        }
    }

    if (i0 + 1 < n) {
        // ---- fast path: 2 full rows = 80B = 5 aligned LDG.128, front-batched ----
        const float4* xv = (const float4*)(x + (size_t)i0 * 10);
        float4 f0 = __ldg(xv + 0);
        float4 f1 = __ldg(xv + 1);
        float4 f2 = __ldg(xv + 2);
        float4 f3 = __ldg(xv + 3);
        float4 f4 = __ldg(xv + 4);
        float2 tv = __ldg((const float2*)(t + i0));   // i0 even -> 8B aligned
        float2 yv = __ldg((const float2*)(y + i0));

        int idx0 =
            ((f0.x != 0.f) << 9) | ((f0.y != 0.f) << 8) |
            ((f0.z != 0.f) << 7) | ((f0.w != 0.f) << 6) |
            ((f1.x != 0.f) << 5) | ((f1.y != 0.f) << 4) |
            ((f1.z != 0.f) << 3) | ((f1.w != 0.f) << 2) |
            ((f2.x != 0.f) << 1) | ((f2.y != 0.f) << 0) |
            ((tv.x != 0.f) << 10);
        int idx1 =
            ((f2.z != 0.f) << 9) | ((f2.w != 0.f) << 8) |
            ((f3.x != 0.f) << 7) | ((f3.y != 0.f) << 6) |
            ((f3.z != 0.f) << 5) | ((f3.w != 0.f) << 4) |
            ((f4.x != 0.f) << 3) | ((f4.y != 0.f) << 2) |
            ((f4.z != 0.f) << 1) | ((f4.w != 0.f) << 0) |
            ((tv.y != 0.f) << 10);

        float2 o;
        o.x = fmaf(yv.x, __ldg(w + idx0), __ldg(b + idx0));
        o.y = fmaf(yv.y, __ldg(w + idx1), __ldg(b + idx1));
        *(float2*)(out + i0) = o;
    } else {
        // ---- tail: single last row ----
        const float* xr = x + (size_t)i0 * 10;
        int idx = 0;
#pragma unroll
        for (int j = 0; j < 10; ++j)
            idx = (idx << 1) | (xr[j] != 0.f ? 1 : 0);
        idx |= (t[i0] != 0.f ? 1 : 0) << 10;
        out[i0] = fmaf(y[i0], __ldg(w + idx), __ldg(b + idx));
    }
}

extern "C" void kernel_launch(void* const* d_in, const int* in_sizes, int n_in,
                              void* d_out, int out_size)
{
    const float* x = (const float*)d_in[0];
    const float* t = (const float*)d_in[1];
    const float* y = (const float*)d_in[2];
    const float* w = (const float*)d_in[3];
    const float* b = (const float*)d_in[4];
    float* out = (float*)d_out;

    int n = in_sizes[1];
    int nthreads = (n + 1) / 2;
    int blocks = (nthreads + TPB - 1) / TPB;
    encoder_direct_pf_kernel<<<blocks, TPB>>>(x, t, y, w, b, out, n);
}